// round 4
// baseline (speedup 1.0000x reference)
#include <cuda_runtime.h>

#define D 128
#define NMAX 50048
#define EMAX 1000000

// Scratch (__device__ globals — allocation-free rule)
__device__ float g_h[NMAX * D];      // h' = dis[r] * (x @ W^T + b)[r]
__device__ float g_dis[NMAX];        // (deg+1)^-0.5
__device__ int   g_degi[NMAX];       // edge count per source
__device__ int   g_cnt[NMAX];        // edge count per target
__device__ int   g_off[NMAX + 1];    // CSR offsets (by target)
__device__ int   g_cur[NMAX];        // fill cursors
__device__ int   g_src[EMAX];        // CSR payload: source index per edge

// ---------------------------------------------------------------------------
__global__ void k_zero(int n) {
    int i = blockIdx.x * blockDim.x + threadIdx.x;
    if (i < n) { g_degi[i] = 0; g_cnt[i] = 0; }
}

__global__ void k_count(const int* __restrict__ ei, int E) {
    int e = blockIdx.x * blockDim.x + threadIdx.x;
    if (e >= E) return;
    atomicAdd(&g_degi[ei[e]], 1);      // source (deg for norm)
    atomicAdd(&g_cnt[ei[E + e]], 1);   // target (CSR)
}

// single-block exclusive scan of g_cnt -> g_off/g_cur, plus dis = rsqrt(deg+1)
__global__ void k_scan(int n) {
    __shared__ int sums[1024];
    int t = threadIdx.x;
    int chunk = (n + 1023) >> 10;
    int lo = t * chunk, hi = min(lo + chunk, n);
    int s = 0;
    for (int i = lo; i < hi; i++) {
        s += g_cnt[i];
        g_dis[i] = rsqrtf((float)(g_degi[i] + 1));  // fused k_dis
    }
    sums[t] = s;
    __syncthreads();
    for (int off = 1; off < 1024; off <<= 1) {
        int v = (t >= off) ? sums[t - off] : 0;
        __syncthreads();
        sums[t] += v;
        __syncthreads();
    }
    int base = (t == 0) ? 0 : sums[t - 1];
    for (int i = lo; i < hi; i++) {
        g_off[i] = base;
        g_cur[i] = base;
        base += g_cnt[i];
    }
    if (t == 1023) g_off[n] = base;
}

__global__ void k_fill(const int* __restrict__ ei, int E) {
    int e = blockIdx.x * blockDim.x + threadIdx.x;
    if (e >= E) return;
    int r = ei[e];
    int c = ei[E + e];
    int pos = atomicAdd(&g_cur[c], 1);
    g_src[pos] = r;
}

// ---------------------------------------------------------------------------
// GEMM: g_h[r][c] = dis[r] * (sum_k x[r][k]*W[c][k] + b[c])
// 128x128 tile per 256-thread block; 8x8 outputs per thread.
// Ws[k][c] fully staged (64KB). xs stored k-major per 16-k chunk, double buffered.
#define XCHUNK 16
#define XBUF (XCHUNK * 128)   // 2048 floats per buffer

__global__ __launch_bounds__(256, 2)
void k_gemm(const float* __restrict__ x, const float* __restrict__ W,
            const float* __restrict__ b, int n) {
    extern __shared__ float sm[];
    float* Ws = sm;                 // [128][128] : Ws[k][c] = W[c][k]
    float* xs = sm + D * D;         // [2][XCHUNK][128] : xs[buf][kl][row]

    int t  = threadIdx.x;
    int tx = t & 15;                // 16 col-groups
    int ty = t >> 4;                // 16 row-groups
    int row0 = blockIdx.x * 128;

    // Load W transposed into Ws[k][c] (conflict-free STS)
    for (int i = t; i < (D * D) / 4; i += 256) {
        int c  = i & 127;
        int k4 = (i >> 7) << 2;
        float4 w = *(const float4*)&W[c * D + k4];
        Ws[(k4 + 0) * D + c] = w.x;
        Ws[(k4 + 1) * D + c] = w.y;
        Ws[(k4 + 2) * D + c] = w.z;
        Ws[(k4 + 3) * D + c] = w.w;
    }

    // Prologue: stage chunk 0 (k-major)
    {
        int j0 = t * 2;
#pragma unroll
        for (int u = 0; u < 2; u++) {
            int j = j0 + u;
            int r = j >> 2;
            int kk = (j & 3) * 4;
            int row = row0 + r;
            float4 v = make_float4(0.f, 0.f, 0.f, 0.f);
            if (row < n) v = *(const float4*)&x[row * D + kk];
            xs[(kk + 0) * 128 + r] = v.x;
            xs[(kk + 1) * 128 + r] = v.y;
            xs[(kk + 2) * 128 + r] = v.z;
            xs[(kk + 3) * 128 + r] = v.w;
        }
    }
    __syncthreads();

    float acc[8][8];
#pragma unroll
    for (int i = 0; i < 8; i++)
#pragma unroll
        for (int j = 0; j < 8; j++) acc[i][j] = 0.f;

    for (int c = 0; c < D / XCHUNK; c++) {
        // Prefetch next chunk into registers
        float4 p[2];
        if (c < D / XCHUNK - 1) {
            int k0 = (c + 1) * XCHUNK;
            int j0 = t * 2;
#pragma unroll
            for (int u = 0; u < 2; u++) {
                int j = j0 + u;
                int r = j >> 2;
                int kk = (j & 3) * 4;
                int row = row0 + r;
                p[u] = make_float4(0.f, 0.f, 0.f, 0.f);
                if (row < n) p[u] = *(const float4*)&x[row * D + k0 + kk];
            }
        }

        const float* xb = &xs[(c & 1) * XBUF];
#pragma unroll
        for (int kl = 0; kl < XCHUNK; kl++) {
            const float* wrow = &Ws[(c * XCHUNK + kl) * D];
            float4 b0 = *(const float4*)&wrow[tx * 4];
            float4 b1 = *(const float4*)&wrow[64 + tx * 4];
            float rA[8];
#pragma unroll
            for (int i = 0; i < 8; i++) rA[i] = xb[kl * 128 + ty * 8 + i];
#pragma unroll
            for (int i = 0; i < 8; i++) {
                acc[i][0] += rA[i] * b0.x;
                acc[i][1] += rA[i] * b0.y;
                acc[i][2] += rA[i] * b0.z;
                acc[i][3] += rA[i] * b0.w;
                acc[i][4] += rA[i] * b1.x;
                acc[i][5] += rA[i] * b1.y;
                acc[i][6] += rA[i] * b1.z;
                acc[i][7] += rA[i] * b1.w;
            }
        }

        if (c < D / XCHUNK - 1) {
            float* dst = &xs[((c + 1) & 1) * XBUF];
            int j0 = t * 2;
#pragma unroll
            for (int u = 0; u < 2; u++) {
                int j = j0 + u;
                int r = j >> 2;
                int kk = (j & 3) * 4;
                dst[(kk + 0) * 128 + r] = p[u].x;
                dst[(kk + 1) * 128 + r] = p[u].y;
                dst[(kk + 2) * 128 + r] = p[u].z;
                dst[(kk + 3) * 128 + r] = p[u].w;
            }
        }
        __syncthreads();
    }

    // Epilogue: += bias, * dis[row], store
    float4 bv0 = *(const float4*)&b[tx * 4];
    float4 bv1 = *(const float4*)&b[64 + tx * 4];
#pragma unroll
    for (int i = 0; i < 8; i++) {
        int row = row0 + ty * 8 + i;
        if (row >= n) break;
        float dv = g_dis[row];
        float4 o0, o1;
        o0.x = (acc[i][0] + bv0.x) * dv;
        o0.y = (acc[i][1] + bv0.y) * dv;
        o0.z = (acc[i][2] + bv0.z) * dv;
        o0.w = (acc[i][3] + bv0.w) * dv;
        o1.x = (acc[i][4] + bv1.x) * dv;
        o1.y = (acc[i][5] + bv1.y) * dv;
        o1.z = (acc[i][6] + bv1.z) * dv;
        o1.w = (acc[i][7] + bv1.w) * dv;
        *(float4*)&g_h[row * D + tx * 4] = o0;
        *(float4*)&g_h[row * D + 64 + tx * 4] = o1;
    }
}

// ---------------------------------------------------------------------------
// Fused gather + self-loop + ReLU + LayerNorm + residual. Warp per node.
// Unrolled x4 for MLP on the dependent index->gather chain.
__global__ void k_agg(const float* __restrict__ x,
                      const float* __restrict__ gamma,
                      const float* __restrict__ beta,
                      float* __restrict__ out, int n) {
    int node = (blockIdx.x * blockDim.x + threadIdx.x) >> 5;
    int lane = threadIdx.x & 31;
    if (node >= n) return;

    float dc = g_dis[node];
    int lo = g_off[node], hi = g_off[node + 1];
    int l4 = lane * 4;

    float4 a0 = make_float4(0.f, 0.f, 0.f, 0.f);
    float4 a1 = make_float4(0.f, 0.f, 0.f, 0.f);

    int i = lo;
    for (; i + 4 <= hi; i += 4) {
        int r0 = g_src[i + 0];
        int r1 = g_src[i + 1];
        int r2 = g_src[i + 2];
        int r3 = g_src[i + 3];
        float4 m0 = *(const float4*)&g_h[r0 * D + l4];
        float4 m1 = *(const float4*)&g_h[r1 * D + l4];
        float4 m2 = *(const float4*)&g_h[r2 * D + l4];
        float4 m3 = *(const float4*)&g_h[r3 * D + l4];
        a0.x += m0.x + m1.x; a0.y += m0.y + m1.y;
        a0.z += m0.z + m1.z; a0.w += m0.w + m1.w;
        a1.x += m2.x + m3.x; a1.y += m2.y + m3.y;
        a1.z += m2.z + m3.z; a1.w += m2.w + m3.w;
    }
    for (; i < hi; i++) {
        int r = g_src[i];
        float4 m = *(const float4*)&g_h[r * D + l4];
        a0.x += m.x; a0.y += m.y; a0.z += m.z; a0.w += m.w;
    }
    // self loop
    float4 hs = *(const float4*)&g_h[node * D + l4];
    float4 v;
    v.x = fmaxf((a0.x + a1.x + hs.x) * dc, 0.f);
    v.y = fmaxf((a0.y + a1.y + hs.y) * dc, 0.f);
    v.z = fmaxf((a0.z + a1.z + hs.z) * dc, 0.f);
    v.w = fmaxf((a0.w + a1.w + hs.w) * dc, 0.f);

    float s  = v.x + v.y + v.z + v.w;
    float ss = v.x * v.x + v.y * v.y + v.z * v.z + v.w * v.w;
#pragma unroll
    for (int o = 16; o; o >>= 1) {
        s  += __shfl_xor_sync(0xffffffffu, s,  o);
        ss += __shfl_xor_sync(0xffffffffu, ss, o);
    }
    float mu  = s * (1.f / 128.f);
    float var = ss * (1.f / 128.f) - mu * mu;
    float inv = rsqrtf(var + 1e-5f);

    float4 g  = *(const float4*)&gamma[l4];
    float4 be = *(const float4*)&beta[l4];
    float4 xv = *(const float4*)&x[node * D + l4];

    float4 o;
    o.x = (v.x - mu) * inv * g.x + be.x + xv.x;
    o.y = (v.y - mu) * inv * g.y + be.y + xv.y;
    o.z = (v.z - mu) * inv * g.z + be.z + xv.z;
    o.w = (v.w - mu) * inv * g.w + be.w + xv.w;
    *(float4*)&out[node * D + l4] = o;
}

// ---------------------------------------------------------------------------
extern "C" void kernel_launch(void* const* d_in, const int* in_sizes, int n_in,
                              void* d_out, int out_size) {
    const float* x     = (const float*)d_in[0];
    const int*   ei    = (const int*)d_in[1];    // int32 (JAX x64 disabled)
    const float* W     = (const float*)d_in[2];
    const float* b     = (const float*)d_in[3];
    const float* gamma = (const float*)d_in[4];
    const float* beta  = (const float*)d_in[5];
    float*       out   = (float*)d_out;

    int n = in_sizes[0] / D;
    int E = in_sizes[1] / 2;

    k_zero<<<(n + 255) / 256, 256>>>(n);
    k_count<<<(E + 255) / 256, 256>>>(ei, E);
    k_scan<<<1, 1024>>>(n);          // also computes g_dis

    int smem = (D * D + 2 * XBUF) * sizeof(float);  // 80 KB
    cudaFuncSetAttribute(k_gemm, cudaFuncAttributeMaxDynamicSharedMemorySize, smem);
    k_gemm<<<(n + 127) / 128, 256, smem>>>(x, W, b, n);

    k_fill<<<(E + 255) / 256, 256>>>(ei, E);

    k_agg<<<(n + 7) / 8, 256>>>(x, gamma, beta, out, n);
}